// round 15
// baseline (speedup 1.0000x reference)
#include <cuda_runtime.h>
#include <cuda_fp16.h>

#define T_TOK 4096
#define DMODEL 1024
#define NEXP 8
#define FFN 2048
#define TOPK 2
#define NPAIR (T_TOK * TOPK)

// ---------------- device scratch ----------------
__device__ int   g_cnt[NEXP];
__device__ int   g_off[NEXP + 1];
__device__ int   g_fill[NEXP];
__device__ int   g_pair_tok[NPAIR];
__device__ float g_pair_gate[NPAIR];
__device__ int   g_top_e[NPAIR];
__device__ float g_top_w[NPAIR];

__device__ __align__(16) __half g_xs_hi[(size_t)T_TOK * DMODEL];
__device__ __align__(16) __half g_wv1[(size_t)NEXP * 2 * FFN * DMODEL];
__device__ __align__(16) __half g_w2t_hi[(size_t)NEXP * DMODEL * FFN];
__device__ __align__(16) __half g_h_hi[(size_t)NPAIR * FFN];

// ---------------- helpers ----------------
__device__ __forceinline__ unsigned smem_u32(const void* p) {
    unsigned a;
    asm("{ .reg .u64 t; cvta.to.shared.u64 t, %1; cvt.u32.u64 %0, t; }"
        : "=r"(a) : "l"(p));
    return a;
}
__device__ __forceinline__ unsigned swz(int row, int c) {
    return (unsigned)(row * 64 + (c ^ ((row & 6) << 3)));
}
__device__ __forceinline__ void ldm4(unsigned* r, unsigned addr) {
    asm volatile("ldmatrix.sync.aligned.m8n8.x4.shared.b16 {%0,%1,%2,%3}, [%4];"
                 : "=r"(r[0]), "=r"(r[1]), "=r"(r[2]), "=r"(r[3]) : "r"(addr));
}
__device__ __forceinline__ void mma16816(float* c, const unsigned* a, const unsigned* b) {
    asm volatile(
        "mma.sync.aligned.m16n8k16.row.col.f32.f16.f16.f32 "
        "{%0,%1,%2,%3}, {%4,%5,%6,%7}, {%8,%9}, {%0,%1,%2,%3};"
        : "+f"(c[0]), "+f"(c[1]), "+f"(c[2]), "+f"(c[3])
        : "r"(a[0]), "r"(a[1]), "r"(a[2]), "r"(a[3]), "r"(b[0]), "r"(b[1]));
}
__device__ __forceinline__ unsigned packh(__half a, __half b) {
    __half2 t = __halves2half2(a, b);
    return *reinterpret_cast<unsigned*>(&t);
}

// -------- router: logits -> top2 -> gates; zeroes out; emits fp16 x ----
__global__ void router_kernel(const float* __restrict__ x, const float* __restrict__ rw,
                              float* __restrict__ out) {
    const int t   = blockIdx.x;
    const int tid = threadIdx.x;
    reinterpret_cast<float4*>(out + (size_t)t * DMODEL)[tid] = make_float4(0.f, 0.f, 0.f, 0.f);

    const float4 xr = reinterpret_cast<const float4*>(x + (size_t)t * DMODEL)[tid];
    {
        unsigned p0 = packh(__float2half_rn(xr.x), __float2half_rn(xr.y));
        unsigned p1 = packh(__float2half_rn(xr.z), __float2half_rn(xr.w));
        reinterpret_cast<uint2*>(g_xs_hi + (size_t)t * DMODEL)[tid] = make_uint2(p0, p1);
    }
    float part[NEXP];
#pragma unroll
    for (int e = 0; e < NEXP; ++e) {
        const float4 w = reinterpret_cast<const float4*>(rw + (size_t)e * DMODEL)[tid];
        part[e] = xr.x * w.x + xr.y * w.y + xr.z * w.z + xr.w * w.w;
    }
#pragma unroll
    for (int e = 0; e < NEXP; ++e)
#pragma unroll
        for (int o = 16; o > 0; o >>= 1)
            part[e] += __shfl_down_sync(0xffffffffu, part[e], o);
    __shared__ float sm[NEXP][8];
    const int warp = tid >> 5, lane = tid & 31;
    if (lane == 0)
#pragma unroll
        for (int e = 0; e < NEXP; ++e) sm[e][warp] = part[e];
    __syncthreads();
    if (tid == 0) {
        float lg[NEXP]; float mx = -1e30f;
#pragma unroll
        for (int e = 0; e < NEXP; ++e) {
            float s = 0.f;
#pragma unroll
            for (int w = 0; w < 8; ++w) s += sm[e][w];
            lg[e] = s; mx = fmaxf(mx, s);
        }
        float den = 0.f;
#pragma unroll
        for (int e = 0; e < NEXP; ++e) { lg[e] = expf(lg[e] - mx); den += lg[e]; }
#pragma unroll
        for (int e = 0; e < NEXP; ++e) lg[e] /= den;
        int e0 = 0; float v0 = lg[0];
#pragma unroll
        for (int e = 1; e < NEXP; ++e) if (lg[e] > v0) { v0 = lg[e]; e0 = e; }
        int e1 = -1; float v1 = -1.f;
#pragma unroll
        for (int e = 0; e < NEXP; ++e)
            if (e != e0 && lg[e] > v1) { v1 = lg[e]; e1 = e; }
        const float nrm = v0 + v1;
        g_top_e[t * 2 + 0] = e0; g_top_w[t * 2 + 0] = v0 / nrm;
        g_top_e[t * 2 + 1] = e1; g_top_w[t * 2 + 1] = v1 / nrm;
        atomicAdd(&g_cnt[e0], 1);
        atomicAdd(&g_cnt[e1], 1);
    }
}

// ---- scatter (single block) ----
__global__ void scatter_kernel() {
    if (threadIdx.x == 0) {
        int r = 0;
        g_off[0] = 0;
        for (int e = 0; e < NEXP; ++e) { r += g_cnt[e]; g_off[e + 1] = r; }
    }
    __syncthreads();
    for (int t = threadIdx.x; t < T_TOK; t += blockDim.x) {
#pragma unroll
        for (int k = 0; k < TOPK; ++k) {
            int e = g_top_e[t * TOPK + k];
            int pos = g_off[e] + atomicAdd(&g_fill[e], 1);
            g_pair_tok[pos]  = t;
            g_pair_gate[pos] = g_top_w[t * TOPK + k];
        }
    }
    __syncthreads();
    if (threadIdx.x < NEXP) { g_cnt[threadIdx.x] = 0; g_fill[threadIdx.x] = 0; }
}

// ------ merged weight prep ------
__global__ void prep_kernel(const float* __restrict__ w1, const float* __restrict__ v1,
                            const float* __restrict__ w2) {
    const int sel = blockIdx.y;
    if (sel < 2) {
        const int i = blockIdx.x * blockDim.x + threadIdx.x;
        const float* s = sel ? v1 : w1;
        float4 v = reinterpret_cast<const float4*>(s)[i];
        unsigned p0 = packh(__float2half_rn(v.x), __float2half_rn(v.y));
        unsigned p1 = packh(__float2half_rn(v.z), __float2half_rn(v.w));
        const int row = i >> 8;
        const int dc  = i & 255;
        const int e = row / FFN, f = row % FFN;
        const size_t drow = (size_t)e * 2 * FFN + 2 * f + sel;
        reinterpret_cast<uint2*>(g_wv1)[drow * 256 + dc] = make_uint2(p0, p1);
    } else {
        __shared__ float t[32][33];
        const int bx = blockIdx.x;
        const int e  = bx >> 11;
        const int rem = bx & 2047;
        const int f0 = (rem & 63) * 32;
        const int d0 = (rem >> 6) * 32;
        const int tx = threadIdx.x & 31, ty = threadIdx.x >> 5;
#pragma unroll
        for (int j = 0; j < 4; ++j)
            t[ty + j * 8][tx] = w2[((size_t)e * FFN + f0 + ty + j * 8) * DMODEL + d0 + tx];
        __syncthreads();
#pragma unroll
        for (int j = 0; j < 4; ++j) {
            const int dl = ty + j * 8;
            g_w2t_hi[((size_t)e * DMODEL + d0 + dl) * FFN + f0 + tx] =
                __float2half_rn(t[tx][dl]);
        }
    }
}

// ---------------- GEMM1 tile constants ----------------
#define G1_STG 16384
#define G1_AH 0
#define G1_BH 8192
#define HST_STRIDE 72

// ---- GEMM1 (fused): 4-stage ring (2 groups x 2 chunks), 2 CTAs/SM ----
__global__ void __launch_bounds__(256, 2) gemm1_kernel() {
    extern __shared__ char smem[];
    __shared__ int toks[128];
    const unsigned sb = smem_u32(smem);
    const int tid = threadIdx.x, lane = tid & 31, wid = tid >> 5;
    const int bx = blockIdx.x;
    const int e = blockIdx.y;
    const int off = g_off[e], cnt = g_off[e + 1] - off;

    const int wm = wid & 1, wn = wid >> 1;
    unsigned aoffs[2][4], boffs[2][2];
#pragma unroll
    for (int ks = 0; ks < 2; ++ks) {
#pragma unroll
        for (int m = 0; m < 4; ++m) {
            int r = wm * 64 + m * 16 + ((lane >> 3) & 1) * 8 + (lane & 7);
            aoffs[ks][m] = swz(r, ((lane >> 4) << 4) + ks * 32);
        }
#pragma unroll
        for (int np = 0; np < 2; ++np) {
            int r = wn * 32 + np * 16 + ((lane >> 4) << 3) + (lane & 7);
            boffs[ks][np] = swz(r, (((lane >> 3) & 1) << 4) + ks * 32);
        }
    }
    const int prow0 = tid >> 2;
    const int pc16 = (tid & 3) * 16;
    const int pc8  = (tid & 3) * 8;
    unsigned soffs[2];
    soffs[0] = swz(prow0, pc16);
    soffs[1] = swz(prow0 + 64, pc16);
    const size_t wvbase = ((size_t)e * 2 * FFN + bx * 128 + prow0) * DMODEL + pc8;

    for (int mt = blockIdx.z; mt * 128 < cnt; mt += gridDim.z) {
        if (tid < 128) {
            int r = mt * 128 + tid;
            toks[tid] = (r < cnt) ? g_pair_tok[off + r] : -1;
        }
        __syncthreads();
        float acc[4][4][4];
#pragma unroll
        for (int m = 0; m < 4; ++m)
#pragma unroll
            for (int n = 0; n < 4; ++n)
#pragma unroll
                for (int q = 0; q < 4; ++q) acc[m][n][q] = 0.f;

        uint4 rAh[2][2], rBh[2][2];
        const uint4 z4 = make_uint4(0, 0, 0, 0);
        // load one 64-k group (2 chunks of 32) into regs
#define G1_LDG(P)                                                                   \
        {                                                                           \
            _Pragma("unroll")                                                       \
            for (int q = 0; q < 2; ++q) {                                           \
                const int K0 = (P) * 64 + q * 32;                                   \
                _Pragma("unroll")                                                   \
                for (int j = 0; j < 2; ++j) {                                       \
                    const int row = prow0 + j * 64;                                 \
                    const int tok = toks[row];                                      \
                    if (tok >= 0) {                                                 \
                        size_t ao = (size_t)tok * DMODEL + K0 + pc8;                \
                        rAh[q][j] = *reinterpret_cast<const uint4*>(g_xs_hi + ao);  \
                    } else { rAh[q][j] = z4; }                                      \
                    rBh[q][j] = *reinterpret_cast<const uint4*>(                    \
                        g_wv1 + wvbase + j * (size_t)(64 * DMODEL) + K0);           \
                }                                                                   \
            }                                                                       \
        }
        G1_LDG(0)
        for (int p = 0; p < DMODEL / 64; ++p) {
            const unsigned sbase = (unsigned)(p & 1) * (2 * G1_STG);
#pragma unroll
            for (int q = 0; q < 2; ++q) {
                const unsigned so = sbase + q * G1_STG;
#pragma unroll
                for (int j = 0; j < 2; ++j) {
                    *reinterpret_cast<uint4*>(smem + so + G1_AH + soffs[j]) = rAh[q][j];
                    *reinterpret_cast<uint4*>(smem + so + G1_BH + soffs[j]) = rBh[q][j];
                }
            }
            if (p + 1 < DMODEL / 64) G1_LDG(p + 1)
            __syncthreads();
#pragma unroll
            for (int q = 0; q < 2; ++q) {
                const unsigned so = sbase + q * G1_STG;
#pragma unroll
                for (int ks = 0; ks < 2; ++ks) {
                    unsigned aH[4][4], bH[2][4];
#pragma unroll
                    for (int m = 0; m < 4; ++m)
                        ldm4(aH[m], sb + so + G1_AH + aoffs[ks][m]);
#pragma unroll
                    for (int np = 0; np < 2; ++np)
                        ldm4(bH[np], sb + so + G1_BH + boffs[ks][np]);
#pragma unroll
                    for (int np = 0; np < 2; ++np)
#pragma unroll
                        for (int hf = 0; hf < 2; ++hf)
#pragma unroll
                            for (int m = 0; m < 4; ++m)
                                mma16816(acc[m][np * 2 + hf], aH[m], &bH[np][hf * 2]);
                }
            }
            // no trailing sync: single-sync ring
        }
        __syncthreads();
        // ---- epilogue: thread-local SwiGLU, stage h tile in smem, coalesced store
        __half* hst = reinterpret_cast<__half*>(smem);
#pragma unroll
        for (int m = 0; m < 4; ++m)
#pragma unroll
            for (int hf = 0; hf < 2; ++hf) {
                const int row = wm * 64 + m * 16 + (lane >> 2) + hf * 8;
#pragma unroll
                for (int n = 0; n < 4; ++n) {
                    const int f = wn * 16 + n * 4 + (lane & 3);
                    const float gv = acc[m][n][hf * 2];
                    const float lv = acc[m][n][hf * 2 + 1];
                    const float hv = gv / (1.f + __expf(-gv)) * lv;
                    hst[row * HST_STRIDE + f] = __float2half_rn(hv);
                }
            }
        __syncthreads();
        {
            const int row = tid >> 1;
            const int c0 = (tid & 1) * 32;
            const int rl = mt * 128 + row;
            if (rl < cnt) {
                const uint4* s4 = reinterpret_cast<const uint4*>(hst + row * HST_STRIDE + c0);
                uint4* d4 = reinterpret_cast<uint4*>(
                    g_h_hi + (size_t)(off + rl) * FFN + bx * 64 + c0);
#pragma unroll
                for (int q = 0; q < 4; ++q) d4[q] = s4[q];
            }
        }
        __syncthreads();
    }
}

// ---------------- GEMM2 tile constants ----------------
#define G2_STG 16384
#define G2_AH 0
#define G2_BH 8192

// ----- GEMM2: 4-stage ring (2 groups x 2 chunks), 2 CTAs/SM -----
__global__ void __launch_bounds__(256, 2) gemm2_kernel(float* __restrict__ out) {
    extern __shared__ char smem[];
    const unsigned sb = smem_u32(smem);
    const int tid = threadIdx.x, lane = tid & 31, wid = tid >> 5;
    const int n0 = blockIdx.x * 128;
    const int e = blockIdx.y;
    const int off = g_off[e], cnt = g_off[e + 1] - off;

    const int wm = wid & 1, wn = wid >> 1;
    unsigned aoffs[2][4], boffs[2][2];
#pragma unroll
    for (int ks = 0; ks < 2; ++ks) {
#pragma unroll
        for (int m = 0; m < 4; ++m) {
            int r = wm * 64 + m * 16 + ((lane >> 3) & 1) * 8 + (lane & 7);
            aoffs[ks][m] = swz(r, ((lane >> 4) << 4) + ks * 32);
        }
#pragma unroll
        for (int np = 0; np < 2; ++np) {
            int r = wn * 32 + np * 16 + ((lane >> 4) << 3) + (lane & 7);
            boffs[ks][np] = swz(r, (((lane >> 3) & 1) << 4) + ks * 32);
        }
    }
    const int prow0 = tid >> 2;
    const int pc16 = (tid & 3) * 16;
    const int pc8  = (tid & 3) * 8;
    unsigned soffs[2];
    soffs[0] = swz(prow0, pc16);
    soffs[1] = swz(prow0 + 64, pc16);

    for (int mt = blockIdx.z; mt * 128 < cnt; mt += gridDim.z) {
        float acc[4][4][4];
#pragma unroll
        for (int m = 0; m < 4; ++m)
#pragma unroll
            for (int n = 0; n < 4; ++n)
#pragma unroll
                for (int q = 0; q < 4; ++q) acc[m][n][q] = 0.f;

        uint4 rAh[2][2], rBh[2][2];
        const uint4 z4 = make_uint4(0, 0, 0, 0);
#define G2_LDG(P)                                                                   \
        {                                                                           \
            _Pragma("unroll")                                                       \
            for (int q = 0; q < 2; ++q) {                                           \
                const int K0 = (P) * 64 + q * 32;                                   \
                _Pragma("unroll")                                                   \
                for (int j = 0; j < 2; ++j) {                                       \
                    const int row = prow0 + j * 64;                                 \
                    const int rl = mt * 128 + row;                                  \
                    if (rl < cnt) {                                                 \
                        size_t ao = (size_t)(off + rl) * FFN + K0 + pc8;            \
                        rAh[q][j] = *reinterpret_cast<const uint4*>(g_h_hi + ao);   \
                    } else { rAh[q][j] = z4; }                                      \
                    size_t bo = ((size_t)e * DMODEL + n0 + row) * FFN + K0 + pc8;   \
                    rBh[q][j] = *reinterpret_cast<const uint4*>(g_w2t_hi + bo);     \
                }                                                                   \
            }                                                                       \
        }
        G2_LDG(0)
        for (int p = 0; p < FFN / 64; ++p) {
            const unsigned sbase = (unsigned)(p & 1) * (2 * G2_STG);
#pragma unroll
            for (int q = 0; q < 2; ++q) {
                const unsigned so = sbase + q * G2_STG;
#pragma unroll
                for (int j = 0; j < 2; ++j) {
                    *reinterpret_cast<uint4*>(smem + so + G2_AH + soffs[j]) = rAh[q][j];
                    *reinterpret_cast<uint4*>(smem + so + G2_BH + soffs[j]) = rBh[q][j];
                }
            }
            if (p + 1 < FFN / 64) G2_LDG(p + 1)
            __syncthreads();
#pragma unroll
            for (int q = 0; q < 2; ++q) {
                const unsigned so = sbase + q * G2_STG;
#pragma unroll
                for (int ks = 0; ks < 2; ++ks) {
                    unsigned aH[4][4], bH[2][4];
#pragma unroll
                    for (int m = 0; m < 4; ++m)
                        ldm4(aH[m], sb + so + G2_AH + aoffs[ks][m]);
#pragma unroll
                    for (int np = 0; np < 2; ++np)
                        ldm4(bH[np], sb + so + G2_BH + boffs[ks][np]);
#pragma unroll
                    for (int np = 0; np < 2; ++np)
#pragma unroll
                        for (int hf = 0; hf < 2; ++hf)
#pragma unroll
                            for (int m = 0; m < 4; ++m)
                                mma16816(acc[m][np * 2 + hf], aH[m], &bH[np][hf * 2]);
                }
            }
            // no trailing sync (single-sync ring)
        }
        // epilogue: gate-scaled atomic combine (2 adds per output elem total)
#pragma unroll
        for (int m = 0; m < 4; ++m)
#pragma unroll
            for (int hf = 0; hf < 2; ++hf) {
                const int rl = mt * 128 + wm * 64 + m * 16 + (lane >> 2) + hf * 8;
                if (rl < cnt) {
                    const int   tok = g_pair_tok[off + rl];
                    const float gt  = g_pair_gate[off + rl];
                    float* dst = out + (size_t)tok * DMODEL + n0 + wn * 32 + (lane & 3) * 2;
#pragma unroll
                    for (int n = 0; n < 4; ++n) {
                        atomicAdd(dst + n * 8 + 0, gt * acc[m][n][hf * 2]);
                        atomicAdd(dst + n * 8 + 1, gt * acc[m][n][hf * 2 + 1]);
                    }
                }
            }
        __syncthreads();
    }
}

// ---------------- launch ----------------
extern "C" void kernel_launch(void* const* d_in, const int* in_sizes, int n_in,
                              void* d_out, int out_size) {
    const float* x  = (const float*)d_in[0];
    const float* w1 = (const float*)d_in[1];
    const float* v1 = (const float*)d_in[2];
    const float* w2 = (const float*)d_in[3];
    const float* rw = (const float*)d_in[4];
    float* out = (float*)d_out;

    cudaFuncSetAttribute(gemm1_kernel, cudaFuncAttributeMaxDynamicSharedMemorySize, 4 * G1_STG);
    cudaFuncSetAttribute(gemm2_kernel, cudaFuncAttributeMaxDynamicSharedMemorySize, 4 * G2_STG);

    router_kernel<<<T_TOK, 256>>>(x, rw, out);                                // 1
    scatter_kernel<<<1, 256>>>();                                             // 2
    prep_kernel<<<dim3(16384, 3), 256>>>(w1, v1, w2);                         // 3
    gemm1_kernel<<<dim3(32, NEXP, 4), 256, 4 * G1_STG>>>();                   // 4 <- profiled
    gemm2_kernel<<<dim3(DMODEL / 128, NEXP, 8), 256, 4 * G2_STG>>>(out);      // 5
}

// round 16
// speedup vs baseline: 1.0848x; 1.0848x over previous
#include <cuda_runtime.h>
#include <cuda_fp16.h>

#define T_TOK 4096
#define DMODEL 1024
#define NEXP 8
#define FFN 2048
#define TOPK 2
#define NPAIR (T_TOK * TOPK)

// ---------------- device scratch ----------------
__device__ int   g_cnt[NEXP];
__device__ int   g_off[NEXP + 1];
__device__ int   g_fill[NEXP];
__device__ int   g_pair_tok[NPAIR];
__device__ float g_pair_gate[NPAIR];
__device__ int   g_top_e[NPAIR];
__device__ float g_top_w[NPAIR];

__device__ __align__(16) __half g_xs_hi[(size_t)T_TOK * DMODEL];
__device__ __align__(16) __half g_wv1[(size_t)NEXP * 2 * FFN * DMODEL];
__device__ __align__(16) __half g_w2t_hi[(size_t)NEXP * DMODEL * FFN];
__device__ __align__(16) __half g_h_hi[(size_t)NPAIR * FFN];

// ---------------- helpers ----------------
__device__ __forceinline__ unsigned smem_u32(const void* p) {
    unsigned a;
    asm("{ .reg .u64 t; cvta.to.shared.u64 t, %1; cvt.u32.u64 %0, t; }"
        : "=r"(a) : "l"(p));
    return a;
}
__device__ __forceinline__ unsigned swz(int row, int c) {
    return (unsigned)(row * 64 + (c ^ ((row & 6) << 3)));
}
__device__ __forceinline__ void ldm4(unsigned* r, unsigned addr) {
    asm volatile("ldmatrix.sync.aligned.m8n8.x4.shared.b16 {%0,%1,%2,%3}, [%4];"
                 : "=r"(r[0]), "=r"(r[1]), "=r"(r[2]), "=r"(r[3]) : "r"(addr));
}
__device__ __forceinline__ void mma16816(float* c, const unsigned* a, const unsigned* b) {
    asm volatile(
        "mma.sync.aligned.m16n8k16.row.col.f32.f16.f16.f32 "
        "{%0,%1,%2,%3}, {%4,%5,%6,%7}, {%8,%9}, {%0,%1,%2,%3};"
        : "+f"(c[0]), "+f"(c[1]), "+f"(c[2]), "+f"(c[3])
        : "r"(a[0]), "r"(a[1]), "r"(a[2]), "r"(a[3]), "r"(b[0]), "r"(b[1]));
}
__device__ __forceinline__ unsigned packh(__half a, __half b) {
    __half2 t = __halves2half2(a, b);
    return *reinterpret_cast<unsigned*>(&t);
}

// -------- router: logits -> top2 -> gates; zeroes out; emits fp16 x ----
__global__ void router_kernel(const float* __restrict__ x, const float* __restrict__ rw,
                              float* __restrict__ out) {
    const int t   = blockIdx.x;
    const int tid = threadIdx.x;
    reinterpret_cast<float4*>(out + (size_t)t * DMODEL)[tid] = make_float4(0.f, 0.f, 0.f, 0.f);

    const float4 xr = reinterpret_cast<const float4*>(x + (size_t)t * DMODEL)[tid];
    {
        unsigned p0 = packh(__float2half_rn(xr.x), __float2half_rn(xr.y));
        unsigned p1 = packh(__float2half_rn(xr.z), __float2half_rn(xr.w));
        reinterpret_cast<uint2*>(g_xs_hi + (size_t)t * DMODEL)[tid] = make_uint2(p0, p1);
    }
    float part[NEXP];
#pragma unroll
    for (int e = 0; e < NEXP; ++e) {
        const float4 w = reinterpret_cast<const float4*>(rw + (size_t)e * DMODEL)[tid];
        part[e] = xr.x * w.x + xr.y * w.y + xr.z * w.z + xr.w * w.w;
    }
#pragma unroll
    for (int e = 0; e < NEXP; ++e)
#pragma unroll
        for (int o = 16; o > 0; o >>= 1)
            part[e] += __shfl_down_sync(0xffffffffu, part[e], o);
    __shared__ float sm[NEXP][8];
    const int warp = tid >> 5, lane = tid & 31;
    if (lane == 0)
#pragma unroll
        for (int e = 0; e < NEXP; ++e) sm[e][warp] = part[e];
    __syncthreads();
    if (tid == 0) {
        float lg[NEXP]; float mx = -1e30f;
#pragma unroll
        for (int e = 0; e < NEXP; ++e) {
            float s = 0.f;
#pragma unroll
            for (int w = 0; w < 8; ++w) s += sm[e][w];
            lg[e] = s; mx = fmaxf(mx, s);
        }
        float den = 0.f;
#pragma unroll
        for (int e = 0; e < NEXP; ++e) { lg[e] = expf(lg[e] - mx); den += lg[e]; }
#pragma unroll
        for (int e = 0; e < NEXP; ++e) lg[e] /= den;
        int e0 = 0; float v0 = lg[0];
#pragma unroll
        for (int e = 1; e < NEXP; ++e) if (lg[e] > v0) { v0 = lg[e]; e0 = e; }
        int e1 = -1; float v1 = -1.f;
#pragma unroll
        for (int e = 0; e < NEXP; ++e)
            if (e != e0 && lg[e] > v1) { v1 = lg[e]; e1 = e; }
        const float nrm = v0 + v1;
        g_top_e[t * 2 + 0] = e0; g_top_w[t * 2 + 0] = v0 / nrm;
        g_top_e[t * 2 + 1] = e1; g_top_w[t * 2 + 1] = v1 / nrm;
        atomicAdd(&g_cnt[e0], 1);
        atomicAdd(&g_cnt[e1], 1);
    }
}

// ---- scatter (single block) ----
__global__ void scatter_kernel() {
    if (threadIdx.x == 0) {
        int r = 0;
        g_off[0] = 0;
        for (int e = 0; e < NEXP; ++e) { r += g_cnt[e]; g_off[e + 1] = r; }
    }
    __syncthreads();
    for (int t = threadIdx.x; t < T_TOK; t += blockDim.x) {
#pragma unroll
        for (int k = 0; k < TOPK; ++k) {
            int e = g_top_e[t * TOPK + k];
            int pos = g_off[e] + atomicAdd(&g_fill[e], 1);
            g_pair_tok[pos]  = t;
            g_pair_gate[pos] = g_top_w[t * TOPK + k];
        }
    }
    __syncthreads();
    if (threadIdx.x < NEXP) { g_cnt[threadIdx.x] = 0; g_fill[threadIdx.x] = 0; }
}

// ------ merged weight prep ------
__global__ void prep_kernel(const float* __restrict__ w1, const float* __restrict__ v1,
                            const float* __restrict__ w2) {
    const int sel = blockIdx.y;
    if (sel < 2) {
        const int i = blockIdx.x * blockDim.x + threadIdx.x;
        const float* s = sel ? v1 : w1;
        float4 v = reinterpret_cast<const float4*>(s)[i];
        unsigned p0 = packh(__float2half_rn(v.x), __float2half_rn(v.y));
        unsigned p1 = packh(__float2half_rn(v.z), __float2half_rn(v.w));
        const int row = i >> 8;
        const int dc  = i & 255;
        const int e = row / FFN, f = row % FFN;
        const size_t drow = (size_t)e * 2 * FFN + 2 * f + sel;
        reinterpret_cast<uint2*>(g_wv1)[drow * 256 + dc] = make_uint2(p0, p1);
    } else {
        __shared__ float t[32][33];
        const int bx = blockIdx.x;
        const int e  = bx >> 11;
        const int rem = bx & 2047;
        const int f0 = (rem & 63) * 32;
        const int d0 = (rem >> 6) * 32;
        const int tx = threadIdx.x & 31, ty = threadIdx.x >> 5;
#pragma unroll
        for (int j = 0; j < 4; ++j)
            t[ty + j * 8][tx] = w2[((size_t)e * FFN + f0 + ty + j * 8) * DMODEL + d0 + tx];
        __syncthreads();
#pragma unroll
        for (int j = 0; j < 4; ++j) {
            const int dl = ty + j * 8;
            g_w2t_hi[((size_t)e * DMODEL + d0 + dl) * FFN + f0 + tx] =
                __float2half_rn(t[tx][dl]);
        }
    }
}

// ---------------- GEMM1 tile constants ----------------
#define G1_STG 16384
#define G1_AH 0
#define G1_BH 8192
#define HST_STRIDE 72

// ---- GEMM1 (fused): 8-stage ring, frag double-buffered mainloop ----
__global__ void __launch_bounds__(256) gemm1_kernel() {
    extern __shared__ char smem[];
    __shared__ int toks[128];
    const unsigned sb = smem_u32(smem);
    const int tid = threadIdx.x, lane = tid & 31, wid = tid >> 5;
    const int bx = blockIdx.x;
    const int e = blockIdx.y;
    const int off = g_off[e], cnt = g_off[e + 1] - off;

    const int wm = wid & 1, wn = wid >> 1;
    unsigned aoffs[2][4], boffs[2][2];
#pragma unroll
    for (int ks = 0; ks < 2; ++ks) {
#pragma unroll
        for (int m = 0; m < 4; ++m) {
            int r = wm * 64 + m * 16 + ((lane >> 3) & 1) * 8 + (lane & 7);
            aoffs[ks][m] = swz(r, ((lane >> 4) << 4) + ks * 32);
        }
#pragma unroll
        for (int np = 0; np < 2; ++np) {
            int r = wn * 32 + np * 16 + ((lane >> 4) << 3) + (lane & 7);
            boffs[ks][np] = swz(r, (((lane >> 3) & 1) << 4) + ks * 32);
        }
    }
    const int prow0 = tid >> 2;
    const int pc16 = (tid & 3) * 16;
    const int pc8  = (tid & 3) * 8;
    unsigned soffs[2];
    soffs[0] = swz(prow0, pc16);
    soffs[1] = swz(prow0 + 64, pc16);
    const size_t wvbase = ((size_t)e * 2 * FFN + bx * 128 + prow0) * DMODEL + pc8;

    for (int mt = blockIdx.z; mt * 128 < cnt; mt += gridDim.z) {
        if (tid < 128) {
            int r = mt * 128 + tid;
            toks[tid] = (r < cnt) ? g_pair_tok[off + r] : -1;
        }
        __syncthreads();
        float acc[4][4][4];
#pragma unroll
        for (int m = 0; m < 4; ++m)
#pragma unroll
            for (int n = 0; n < 4; ++n)
#pragma unroll
                for (int q = 0; q < 4; ++q) acc[m][n][q] = 0.f;

        uint4 rAh[4][2], rBh[4][2];
        const uint4 z4 = make_uint4(0, 0, 0, 0);
#define G1_LDG(P)                                                                   \
        {                                                                           \
            _Pragma("unroll")                                                       \
            for (int q = 0; q < 4; ++q) {                                           \
                const int K0 = (P) * 128 + q * 32;                                  \
                _Pragma("unroll")                                                   \
                for (int j = 0; j < 2; ++j) {                                       \
                    const int row = prow0 + j * 64;                                 \
                    const int tok = toks[row];                                      \
                    if (tok >= 0) {                                                 \
                        size_t ao = (size_t)tok * DMODEL + K0 + pc8;                \
                        rAh[q][j] = *reinterpret_cast<const uint4*>(g_xs_hi + ao);  \
                    } else { rAh[q][j] = z4; }                                      \
                    rBh[q][j] = *reinterpret_cast<const uint4*>(                    \
                        g_wv1 + wvbase + j * (size_t)(64 * DMODEL) + K0);           \
                }                                                                   \
            }                                                                       \
        }
        // fragment load for ks-block kk (0..7) of the current group
        unsigned fA[2][4][4], fB[2][2][4];
#define G1_LDFRAG(BUF, SBASE, KK)                                                   \
        {                                                                           \
            const unsigned so_ = (SBASE) + ((KK) >> 1) * G1_STG;                    \
            const int ks_ = (KK) & 1;                                               \
            _Pragma("unroll")                                                       \
            for (int m = 0; m < 4; ++m)                                             \
                ldm4(fA[BUF][m], sb + so_ + G1_AH + aoffs[ks_][m]);                 \
            _Pragma("unroll")                                                       \
            for (int np = 0; np < 2; ++np)                                          \
                ldm4(fB[BUF][np], sb + so_ + G1_BH + boffs[ks_][np]);               \
        }
#define G1_MMA(BUF)                                                                 \
        {                                                                           \
            _Pragma("unroll")                                                       \
            for (int np = 0; np < 2; ++np)                                          \
                _Pragma("unroll")                                                   \
                for (int hf = 0; hf < 2; ++hf)                                      \
                    _Pragma("unroll")                                               \
                    for (int m = 0; m < 4; ++m)                                     \
                        mma16816(acc[m][np * 2 + hf], fA[BUF][m], &fB[BUF][np][hf * 2]); \
        }
        G1_LDG(0)
        for (int p = 0; p < DMODEL / 128; ++p) {
            const unsigned sbase = (unsigned)(p & 1) * (4 * G1_STG);
#pragma unroll
            for (int q = 0; q < 4; ++q) {
                const unsigned so = sbase + q * G1_STG;
#pragma unroll
                for (int j = 0; j < 2; ++j) {
                    *reinterpret_cast<uint4*>(smem + so + G1_AH + soffs[j]) = rAh[q][j];
                    *reinterpret_cast<uint4*>(smem + so + G1_BH + soffs[j]) = rBh[q][j];
                }
            }
            if (p + 1 < DMODEL / 128) G1_LDG(p + 1)
            __syncthreads();
            G1_LDFRAG(0, sbase, 0)
#pragma unroll
            for (int kk = 0; kk < 8; ++kk) {
                if (kk < 7) G1_LDFRAG((kk + 1) & 1, sbase, kk + 1)
                G1_MMA(kk & 1)
            }
            // no trailing sync: single-sync ring
        }
        __syncthreads();
        // ---- epilogue: thread-local SwiGLU, stage h tile in smem, coalesced store
        __half* hst = reinterpret_cast<__half*>(smem);
#pragma unroll
        for (int m = 0; m < 4; ++m)
#pragma unroll
            for (int hf = 0; hf < 2; ++hf) {
                const int row = wm * 64 + m * 16 + (lane >> 2) + hf * 8;
#pragma unroll
                for (int n = 0; n < 4; ++n) {
                    const int f = wn * 16 + n * 4 + (lane & 3);
                    const float gv = acc[m][n][hf * 2];
                    const float lv = acc[m][n][hf * 2 + 1];
                    const float hv = gv / (1.f + __expf(-gv)) * lv;
                    hst[row * HST_STRIDE + f] = __float2half_rn(hv);
                }
            }
        __syncthreads();
        {
            const int row = tid >> 1;
            const int c0 = (tid & 1) * 32;
            const int rl = mt * 128 + row;
            if (rl < cnt) {
                const uint4* s4 = reinterpret_cast<const uint4*>(hst + row * HST_STRIDE + c0);
                uint4* d4 = reinterpret_cast<uint4*>(
                    g_h_hi + (size_t)(off + rl) * FFN + bx * 64 + c0);
#pragma unroll
                for (int q = 0; q < 4; ++q) d4[q] = s4[q];
            }
        }
        __syncthreads();
    }
}

// ---------------- GEMM2 tile constants ----------------
#define G2_STG 16384
#define G2_AH 0
#define G2_BH 8192

// ----- GEMM2: 8-stage ring, frag double-buffered mainloop -----
__global__ void __launch_bounds__(256) gemm2_kernel(float* __restrict__ out) {
    extern __shared__ char smem[];
    const unsigned sb = smem_u32(smem);
    const int tid = threadIdx.x, lane = tid & 31, wid = tid >> 5;
    const int n0 = blockIdx.x * 128;
    const int e = blockIdx.y;
    const int off = g_off[e], cnt = g_off[e + 1] - off;

    const int wm = wid & 1, wn = wid >> 1;
    unsigned aoffs[2][4], boffs[2][2];
#pragma unroll
    for (int ks = 0; ks < 2; ++ks) {
#pragma unroll
        for (int m = 0; m < 4; ++m) {
            int r = wm * 64 + m * 16 + ((lane >> 3) & 1) * 8 + (lane & 7);
            aoffs[ks][m] = swz(r, ((lane >> 4) << 4) + ks * 32);
        }
#pragma unroll
        for (int np = 0; np < 2; ++np) {
            int r = wn * 32 + np * 16 + ((lane >> 4) << 3) + (lane & 7);
            boffs[ks][np] = swz(r, (((lane >> 3) & 1) << 4) + ks * 32);
        }
    }
    const int prow0 = tid >> 2;
    const int pc16 = (tid & 3) * 16;
    const int pc8  = (tid & 3) * 8;
    unsigned soffs[2];
    soffs[0] = swz(prow0, pc16);
    soffs[1] = swz(prow0 + 64, pc16);

    for (int mt = blockIdx.z; mt * 128 < cnt; mt += gridDim.z) {
        float acc[4][4][4];
#pragma unroll
        for (int m = 0; m < 4; ++m)
#pragma unroll
            for (int n = 0; n < 4; ++n)
#pragma unroll
                for (int q = 0; q < 4; ++q) acc[m][n][q] = 0.f;

        uint4 rAh[4][2], rBh[4][2];
        const uint4 z4 = make_uint4(0, 0, 0, 0);
#define G2_LDG(P)                                                                   \
        {                                                                           \
            _Pragma("unroll")                                                       \
            for (int q = 0; q < 4; ++q) {                                           \
                const int K0 = (P) * 128 + q * 32;                                  \
                _Pragma("unroll")                                                   \
                for (int j = 0; j < 2; ++j) {                                       \
                    const int row = prow0 + j * 64;                                 \
                    const int rl = mt * 128 + row;                                  \
                    if (rl < cnt) {                                                 \
                        size_t ao = (size_t)(off + rl) * FFN + K0 + pc8;            \
                        rAh[q][j] = *reinterpret_cast<const uint4*>(g_h_hi + ao);   \
                    } else { rAh[q][j] = z4; }                                      \
                    size_t bo = ((size_t)e * DMODEL + n0 + row) * FFN + K0 + pc8;   \
                    rBh[q][j] = *reinterpret_cast<const uint4*>(g_w2t_hi + bo);     \
                }                                                                   \
            }                                                                       \
        }
        unsigned fA[2][4][4], fB[2][2][4];
#define G2_LDFRAG(BUF, SBASE, KK)                                                   \
        {                                                                           \
            const unsigned so_ = (SBASE) + ((KK) >> 1) * G2_STG;                    \
            const int ks_ = (KK) & 1;                                               \
            _Pragma("unroll")                                                       \
            for (int m = 0; m < 4; ++m)                                             \
                ldm4(fA[BUF][m], sb + so_ + G2_AH + aoffs[ks_][m]);                 \
            _Pragma("unroll")                                                       \
            for (int np = 0; np < 2; ++np)                                          \
                ldm4(fB[BUF][np], sb + so_ + G2_BH + boffs[ks_][np]);               \
        }
#define G2_MMA(BUF)                                                                 \
        {                                                                           \
            _Pragma("unroll")                                                       \
            for (int np = 0; np < 2; ++np)                                          \
                _Pragma("unroll")                                                   \
                for (int hf = 0; hf < 2; ++hf)                                      \
                    _Pragma("unroll")                                               \
                    for (int m = 0; m < 4; ++m)                                     \
                        mma16816(acc[m][np * 2 + hf], fA[BUF][m], &fB[BUF][np][hf * 2]); \
        }
        G2_LDG(0)
        for (int p = 0; p < FFN / 128; ++p) {
            const unsigned sbase = (unsigned)(p & 1) * (4 * G2_STG);
#pragma unroll
            for (int q = 0; q < 4; ++q) {
                const unsigned so = sbase + q * G2_STG;
#pragma unroll
                for (int j = 0; j < 2; ++j) {
                    *reinterpret_cast<uint4*>(smem + so + G2_AH + soffs[j]) = rAh[q][j];
                    *reinterpret_cast<uint4*>(smem + so + G2_BH + soffs[j]) = rBh[q][j];
                }
            }
            if (p + 1 < FFN / 128) G2_LDG(p + 1)
            __syncthreads();
            G2_LDFRAG(0, sbase, 0)
#pragma unroll
            for (int kk = 0; kk < 8; ++kk) {
                if (kk < 7) G2_LDFRAG((kk + 1) & 1, sbase, kk + 1)
                G2_MMA(kk & 1)
            }
            // no trailing sync (single-sync ring)
        }
        // epilogue: gate-scaled atomic combine (2 adds per output elem total)
#pragma unroll
        for (int m = 0; m < 4; ++m)
#pragma unroll
            for (int hf = 0; hf < 2; ++hf) {
                const int rl = mt * 128 + wm * 64 + m * 16 + (lane >> 2) + hf * 8;
                if (rl < cnt) {
                    const int   tok = g_pair_tok[off + rl];
                    const float gt  = g_pair_gate[off + rl];
                    float* dst = out + (size_t)tok * DMODEL + n0 + wn * 32 + (lane & 3) * 2;
#pragma unroll
                    for (int n = 0; n < 4; ++n) {
                        atomicAdd(dst + n * 8 + 0, gt * acc[m][n][hf * 2]);
                        atomicAdd(dst + n * 8 + 1, gt * acc[m][n][hf * 2 + 1]);
                    }
                }
            }
        __syncthreads();
    }
}

// ---------------- launch ----------------
extern "C" void kernel_launch(void* const* d_in, const int* in_sizes, int n_in,
                              void* d_out, int out_size) {
    const float* x  = (const float*)d_in[0];
    const float* w1 = (const float*)d_in[1];
    const float* v1 = (const float*)d_in[2];
    const float* w2 = (const float*)d_in[3];
    const float* rw = (const float*)d_in[4];
    float* out = (float*)d_out;

    cudaFuncSetAttribute(gemm1_kernel, cudaFuncAttributeMaxDynamicSharedMemorySize, 8 * G1_STG);
    cudaFuncSetAttribute(gemm2_kernel, cudaFuncAttributeMaxDynamicSharedMemorySize, 8 * G2_STG);

    router_kernel<<<T_TOK, 256>>>(x, rw, out);                                // 1
    scatter_kernel<<<1, 256>>>();                                             // 2
    prep_kernel<<<dim3(16384, 3), 256>>>(w1, v1, w2);                         // 3
    gemm1_kernel<<<dim3(32, NEXP, 4), 256, 8 * G1_STG>>>();                   // 4 <- profiled
    gemm2_kernel<<<dim3(DMODEL / 128, NEXP, 8), 256, 8 * G2_STG>>>(out);      // 5
}